// round 17
// baseline (speedup 1.0000x reference)
#include <cuda_runtime.h>
#include <math.h>

// Chamfer loss, B=4, C=3, Np=Ng=8192. R17 = R16 machinery with 128-thread
// blocks: TPQ=64, ty in [0,8), RP stays 8 -> per-thread slots per stage are
// IDENTICAL to the champion core, but launch_bounds(128,6) yields up to 24
// warps/SM (6/SMSP vs 4). 512 blocks in a single wave (888 resident slots).
//  Evidence: R16 profile: issue=60.4% at 4 warps/SMSP -> no-eligible-warp
//  stalls dominate; R12 failed because it halved per-thread work, this keeps it.
//  - col mins complement-encoded (atomicMax of 0x7f7fffff - bits): zero-init
//    == FLT_MAX, no init kernel, order-independent => deterministic.
//  - per-batch ticket finalize (overlapped) + global ticket writes out/resets.

#define BATCH   4
#define NPT     8192
#define TPQ     64                       // predict points per block
#define TGQ     128                      // gt points per stage
#define NSTAGES (NPT / TGQ)              // 64
#define NTH     128                      // 16 (g=tx) x 8 (p=ty)
#define NBLK_B  (NPT / TPQ)              // 128 blocks per batch
#define EPSF    1e-12f
#define FPSCALE 4294967296.0             // 2^32 fixed point

__device__ unsigned int       g_colmax[BATCH * NPT];   // complement bits (0 = FLT_MAX)
__device__ unsigned long long g_acc;                   // fixed-point total (rows + cols)
__device__ unsigned int       g_done_b[BATCH];         // per-batch completion counters
__device__ unsigned int       g_done_all;              // batch-finalizer counter

__global__ __launch_bounds__(NTH, 6)
void chamfer_main(const float* __restrict__ P, const float* __restrict__ G,
                  float* __restrict__ out) {
    const int b     = blockIdx.y;
    const int pbase = blockIdx.x * TPQ;
    const float* Pb = P + (size_t)b * 3 * NPT;
    const float* Gb = G + (size_t)b * 3 * NPT;
    const int tid = threadIdx.x;
    const int tx  = tid & 15;        // g direction
    const int ty  = tid >> 4;        // p direction (0..7)

    __shared__ float4 sp[TPQ];
    __shared__ float4 sg[2][TGQ];               // double buffer
    __shared__ float  cbuf[2][8][TGQ + 1];      // double buffer, padded
    __shared__ float  sred[NTH];
    __shared__ unsigned int ticket;

    // ---- prologue: prefetch stage-0 gt (1 pt/thread, no divergence), p tile ----
    float rx = Gb[tid];
    float ry = Gb[NPT + tid];
    float rz = Gb[2 * NPT + tid];
    if (tid < TPQ) {
        float px = Pb[pbase + tid];
        float py = Pb[NPT + pbase + tid];
        float pz = Pb[2 * NPT + pbase + tid];
        sp[tid] = make_float4(-2.f * px, -2.f * py, -2.f * pz,
                              px * px + py * py + pz * pz);
    }
    sg[0][tid] = make_float4(rx, ry, rz, rx * rx + ry * ry + rz * rz);
    __syncthreads();

    float pa[8], pb_[8], pc[8], pp2[8], rowmin[8];
#pragma unroll
    for (int ii = 0; ii < 8; ii++) {
        float4 v = sp[ty * 8 + ii];
        pa[ii] = v.x; pb_[ii] = v.y; pc[ii] = v.z; pp2[ii] = v.w;
        rowmin[ii] = 3.4e38f;
    }

    for (int s = 0; s < NSTAGES; s++) {
        const int cur = s & 1, nxt = cur ^ 1;

        // issue next-stage gmem loads now; latency hidden under compute
        if (s + 1 < NSTAGES) {
            int g = (s + 1) * TGQ + tid;
            rx = Gb[g]; ry = Gb[NPT + g]; rz = Gb[2 * NPT + g];
        }

        // two g-passes of 64 columns each (RG=4) to keep registers small
#pragma unroll
        for (int h = 0; h < 2; h++) {
            float gx[4], gy[4], gz[4], g2[4], colmin[4];
#pragma unroll
            for (int jj = 0; jj < 4; jj++) {
                float4 v = sg[cur][h * 64 + jj * 16 + tx];
                gx[jj] = v.x; gy[jj] = v.y; gz[jj] = v.z; g2[jj] = v.w;
                colmin[jj] = 3.4e38f;
            }

#pragma unroll
            for (int ii = 0; ii < 8; ii++) {
#pragma unroll
                for (int jj = 0; jj < 4; jj++) {
                    float e = fmaf(pc[ii], gz[jj], g2[jj]);
                    e = fmaf(pb_[ii], gy[jj], e);
                    e = fmaf(pa[ii], gx[jj], e);
                    rowmin[ii] = fminf(rowmin[ii], e);
                    colmin[jj] = fminf(colmin[jj], e + pp2[ii]);
                }
            }

            // per-warp-row column partials (pre-barrier stores)
#pragma unroll
            for (int jj = 0; jj < 4; jj++)
                cbuf[cur][ty][h * 64 + jj * 16 + tx] = colmin[jj];
        }

        // stage s+1 gt chunk -> other smem buffer (prefetch regs landed)
        if (s + 1 < NSTAGES)
            sg[nxt][tid] = make_float4(rx, ry, rz, rx * rx + ry * ry + rz * rz);

        __syncthreads();   // the ONLY barrier per stage

        // column reduce: all 128 threads, one g column each; overlaps next
        // stage's compute in other warps (cbuf double-buffered)
        {
            float v[8];
#pragma unroll
            for (int t = 0; t < 8; t++) v[t] = cbuf[cur][t][tid];
#pragma unroll
            for (int st = 4; st > 0; st >>= 1)
#pragma unroll
                for (int t = 0; t < 4; t++)
                    if (t < st) v[t] = fminf(v[t], v[t + st]);
            float m = fmaxf(v[0], EPSF);   // clamp (ref); positive bits
            atomicMax(&g_colmax[b * NPT + s * TGQ + tid],
                      0x7f7fffffu - (unsigned int)__float_as_int(m));
        }
    }

    // row-min reduce across tx (intra-warp: lanes differing in bits 0-3 share
    // ty and partition the g columns), sqrt, block-sum
#pragma unroll
    for (int ii = 0; ii < 8; ii++) {
        float m = rowmin[ii];
#pragma unroll
        for (int off = 1; off < 16; off <<= 1)
            m = fminf(m, __shfl_xor_sync(0xffffffffu, m, off));
        rowmin[ii] = m;
    }

    float rsum = 0.f;
    if (tx == 0) {
#pragma unroll
        for (int ii = 0; ii < 8; ii++)
            rsum += sqrtf(fmaxf(rowmin[ii] + pp2[ii], EPSF));
    }

    sred[tid] = rsum;
    __syncthreads();
    for (int st = NTH / 2; st > 0; st >>= 1) {
        if (tid < st) sred[tid] += sred[tid + st];
        __syncthreads();
    }
    if (tid == 0) {
        unsigned long long fx =
            (unsigned long long)((double)sred[0] * FPSCALE + 0.5);
        atomicAdd(&g_acc, fx);             // integer add: deterministic
    }

    // ---- hierarchical finalize ----
    __threadfence();        // each thread: its REDG atomics reach L2
    __syncthreads();        // block-wide: all fences done before the ticket
    if (tid == 0)
        ticket = atomicAdd(&g_done_b[b], 1u);
    __syncthreads();

    if (ticket == NBLK_B - 1) {
        // last block of THIS batch: finalize this batch's 8192 columns
        // (overlapped with other batches' compute). 2048 uint4 / 128 thr.
        uint4* cm4 = reinterpret_cast<uint4*>(g_colmax + (size_t)b * NPT);
        const uint4 z4 = make_uint4(0u, 0u, 0u, 0u);
        float s = 0.f;
#pragma unroll 4
        for (int i = tid; i < NPT / 4; i += NTH) {
            uint4 c = __ldcg(&cm4[i]);
            s += sqrtf(__int_as_float((int)(0x7f7fffffu - c.x)));
            s += sqrtf(__int_as_float((int)(0x7f7fffffu - c.y)));
            s += sqrtf(__int_as_float((int)(0x7f7fffffu - c.z)));
            s += sqrtf(__int_as_float((int)(0x7f7fffffu - c.w)));
            cm4[i] = z4;                                         // reset for replay
        }
        sred[tid] = s;
        __syncthreads();
        for (int st = NTH / 2; st > 0; st >>= 1) {
            if (tid < st) sred[tid] += sred[tid + st];
            __syncthreads();
        }
        if (tid == 0) {
            unsigned long long fx =
                (unsigned long long)((double)sred[0] * FPSCALE + 0.5);
            atomicAdd(&g_acc, fx);
            g_done_b[b] = 0u;              // reset this batch's counter
            __threadfence();
            unsigned int t2 = atomicAdd(&g_done_all, 1u);
            if (t2 == BATCH - 1) {
                unsigned long long tot = atomicAdd(&g_acc, 0ull);  // fenced-in read
                out[0] = (float)((double)tot / FPSCALE
                                 / (double)(BATCH * 2 * NPT));     // denom = B*(Np+Ng)
                g_acc      = 0ull;         // reset
                g_done_all = 0u;           // reset
            }
        }
    }
}

extern "C" void kernel_launch(void* const* d_in, const int* in_sizes, int n_in,
                              void* d_out, int out_size) {
    const float* P = (const float*)d_in[0];
    const float* G = (const float*)d_in[1];

    dim3 grid(NPT / TPQ, BATCH);             // 128 x 4 = 512 blocks, ONE launch
    chamfer_main<<<grid, NTH>>>(P, G, (float*)d_out);
}